// round 6
// baseline (speedup 1.0000x reference)
#include <cuda_runtime.h>
#include <math.h>
#include <stdint.h>

// Problem dims
#define BB 128
#define TT 512
#define II 300
#define HH 256
#define G4 1024   // 4*H

// persist geometry
#define CL 8           // CTAs per cluster
#define NCLUS 16       // clusters
#define WS 300         // W_s row stride (floats): 300 mod 32 = 12 -> lane-distinct
                       // .128 rows tile all 32 banks per phase (perfect)
#define HS 264         // h_s row stride (floats) - h loads are uniform-broadcast
#define PS 9           // ps batch stride (9 coprime 32 -> conflict-free)

// Scratch (device globals — no allocations allowed)
__device__ float g_xp[(size_t)TT * BB * G4];   // [t][b][gate]  (256 MB)
__device__ float g_hf[BB * HH];                // forward-dir final hidden
__device__ float g_hb[BB * HH];                // backward-dir final hidden

__device__ __forceinline__ float fast_sigmoid(float v) {
    return 1.0f / (1.0f + __expf(-v));
}
__device__ __forceinline__ float fast_tanh(float v) {
    return __fdividef(2.0f, 1.0f + __expf(-2.0f * v)) - 1.0f;
}

// packed dual-fp32 FMA
__device__ __forceinline__ void fma2(float2& acc, float2 a, float2 b) {
    asm("fma.rn.f32x2 %0, %1, %2, %0;"
        : "+l"(reinterpret_cast<unsigned long long&>(acc))
        : "l"(reinterpret_cast<unsigned long long&>(a)),
          "l"(reinterpret_cast<unsigned long long&>(b)));
}

__device__ __forceinline__ void st_remote_f32(uint32_t saddr, uint32_t trank, float v) {
    uint32_t ra;
    asm volatile("mapa.shared::cluster.u32 %0, %1, %2;" : "=r"(ra) : "r"(saddr), "r"(trank));
    asm volatile("st.shared::cluster.f32 [%0], %1;" :: "r"(ra), "f"(v) : "memory");
}

// ---------------------------------------------------------------------------
// xp GEMM: xp[t][b][n] = sum_i x[b][t][i] * W_ih_f[n][i] + b_f[n]
// ---------------------------------------------------------------------------
__global__ void xp_gemm(const float* __restrict__ A,
                        const float* __restrict__ W,
                        const float* __restrict__ bias) {
    __shared__ float As[8][132];
    __shared__ float Bs[8][132];

    const int nt = blockIdx.x;
    const int mt = blockIdx.y;
    const int tid = threadIdx.x;
    const int tx = tid & 15;
    const int ty = tid >> 4;

    const int m0 = mt * 128;
    const int n0 = nt * 128;

    float2 acc2[4][8];
#pragma unroll
    for (int ip = 0; ip < 4; ip++)
#pragma unroll
        for (int j = 0; j < 8; j++) acc2[ip][j] = make_float2(0.f, 0.f);

    for (int k0 = 0; k0 < II; k0 += 8) {
#pragma unroll
        for (int e = tid; e < 1024; e += 256) {
            int r = e >> 3;
            int kk = e & 7;
            int k = k0 + kk;
            As[kk][r] = (k < II) ? A[(size_t)(m0 + r) * II + k] : 0.0f;
            Bs[kk][r] = (k < II) ? W[(size_t)(n0 + r) * II + k] : 0.0f;
        }
        __syncthreads();

#pragma unroll
        for (int kk = 0; kk < 8; kk++) {
            float4 a0 = *(const float4*)&As[kk][ty * 8];
            float4 a1 = *(const float4*)&As[kk][ty * 8 + 4];
            float4 b0 = *(const float4*)&Bs[kk][tx * 8];
            float4 b1 = *(const float4*)&Bs[kk][tx * 8 + 4];
            float2 ap[4] = { {a0.x, a0.y}, {a0.z, a0.w}, {a1.x, a1.y}, {a1.z, a1.w} };
            float bj[8] = { b0.x, b0.y, b0.z, b0.w, b1.x, b1.y, b1.z, b1.w };
#pragma unroll
            for (int j = 0; j < 8; j++) {
                float2 bb = make_float2(bj[j], bj[j]);
#pragma unroll
                for (int ip = 0; ip < 4; ip++) fma2(acc2[ip][j], ap[ip], bb);
            }
        }
        __syncthreads();
    }

#pragma unroll
    for (int i = 0; i < 8; i++) {
        int m = m0 + ty * 8 + i;
        int bidx = m >> 9;
        int t = m & 511;
        size_t base = ((size_t)t * BB + bidx) * G4;
#pragma unroll
        for (int j = 0; j < 8; j++) {
            int n = n0 + tx * 8 + j;
            float v = (i & 1) ? acc2[i >> 1][j].y : acc2[i >> 1][j].x;
            g_xp[base + n] = v + bias[n];
        }
    }
}

// ---------------------------------------------------------------------------
// Backward direction: only ONE step matters (h0=c0=0 on x[:, T-1]).
// ---------------------------------------------------------------------------
__global__ void bwd_last(const float* __restrict__ x,
                         const float* __restrict__ Wb,
                         const float* __restrict__ bb) {
    const int b = blockIdx.x;
    const int tid = threadIdx.x;
    __shared__ float xs[304];
    __shared__ float gs[G4];

    const float* xr = x + ((size_t)b * TT + (TT - 1)) * II;
    for (int i = tid; i < II; i += 256) xs[i] = xr[i];
    __syncthreads();

    const int wid = tid >> 5;
    const int lane = tid & 31;
    for (int r = wid; r < G4; r += 8) {
        float s = 0.0f;
        const float* wr = Wb + (size_t)r * II;
        for (int i = lane; i < II; i += 32) s += xs[i] * wr[i];
#pragma unroll
        for (int off = 16; off > 0; off >>= 1)
            s += __shfl_down_sync(0xffffffffu, s, off);
        if (lane == 0) gs[r] = s + bb[r];
    }
    __syncthreads();

    if (tid < HH) {
        float ig = 1.0f / (1.0f + expf(-gs[tid]));
        float gg = tanhf(gs[512 + tid]);
        float og = 1.0f / (1.0f + expf(-gs[768 + tid]));
        float c = ig * gg;
        g_hb[b * HH + tid] = og * tanhf(c);
    }
}

// ---------------------------------------------------------------------------
// Persistent forward recurrence. 16 clusters x 8 CTAs; cluster = 8 batches.
// CTA rank holds W rows {g*256 + rank*32 + u : g<4, u<32} = 128 rows x K=256
// in smem for the whole kernel (stride 300 floats: 12 mod 32 -> phase-perfect
// lane-distinct .128 loads). h[2][8][264] double-buffered in every CTA's
// smem; exchanged via st.shared::cluster + one barrier.cluster per step.
//
// 512 threads. Mainloop role: rr = tid&127 (W row, lane-distinct), ks =
// tid>>7 (K quarter of 64). Thread: 1 row x 64 k x 8 batches, acc packed
// f32x2 over k. Partials -> ps[ks][rr][b] (stride 9, conflict-free).
// Finalize role (tid<128): u = tid>>2, bq = tid&3 -> batches bq, bq+4;
// gathers 4 gates x 4 ks, adds xp (prefetched), updates register c,
// scatters h to all 8 cluster CTAs.
// ---------------------------------------------------------------------------
__global__ void __launch_bounds__(512, 1) __cluster_dims__(CL, 1, 1)
lstm_persist(const float* __restrict__ Whh) {
    extern __shared__ float sm[];
    float* W_s = sm;                          // [128][WS]
    float* h_s = sm + 128 * WS;               // [2][8][HS]
    float* ps  = h_s + 2 * 8 * HS;            // [4][128][PS]

    const int tid = threadIdx.x;
    uint32_t rank;
    asm("mov.u32 %0, %%cluster_ctarank;" : "=r"(rank));
    const int cid = blockIdx.x >> 3;

    // ---- load W slice once: local row lr = g*32+u -> global g*256 + rank*32 + u
    for (int idx = tid; idx < 128 * 64; idx += 512) {
        int lr = idx >> 6;
        int k4 = idx & 63;
        int grow = (lr >> 5) * HH + (int)rank * 32 + (lr & 31);
        float4 v = *(const float4*)&Whh[(size_t)grow * HH + k4 * 4];
        *(float4*)&W_s[lr * WS + k4 * 4] = v;
    }
    // zero h buffer 0 (buffer 1 fully overwritten every step)
    for (int i = tid; i < 8 * HS; i += 512) h_s[i] = 0.0f;
    __syncthreads();
    asm volatile("barrier.cluster.arrive.aligned;" ::: "memory");
    asm volatile("barrier.cluster.wait.aligned;" ::: "memory");

    const int rr = tid & 127;
    const int ks = tid >> 7;                  // 0..3
    const int u = tid >> 2;                   // finalize: hidden unit (tid<128)
    const int bq = tid & 3;                   // finalize: batch quad
    const int kglob = (int)rank * 32 + u;
    const int b0 = cid * CL + bq;
    float c0 = 0.f, c1 = 0.f, h0v = 0.f, h1v = 0.f;

    const uint32_t h_sh_base = (uint32_t)__cvta_generic_to_shared(h_s);
    const float* wrow = W_s + rr * WS + ks * 64;

    for (int t = 0; t < TT; t++) {
        const int cur = t & 1;
        const float* __restrict__ hb = h_s + cur * 8 * HS + ks * 64;

        // prefetch xp (finalize threads; consumed after mainloop)
        float xr0[4], xr1[4];
        if (tid < 128) {
            size_t xb = ((size_t)t * BB + b0) * G4 + kglob;
#pragma unroll
            for (int g = 0; g < 4; g++) {
                xr0[g] = __ldg(&g_xp[xb + g * 256]);
                xr1[g] = __ldg(&g_xp[xb + (size_t)4 * G4 + g * 256]);
            }
        }

        // mainloop: 1 row x 64 k x 8 batches; f32x2 packed over k
        float2 acc[8];
#pragma unroll
        for (int b = 0; b < 8; b++) acc[b] = make_float2(0.f, 0.f);
#pragma unroll
        for (int k4 = 0; k4 < 16; k4++) {
            float4 w = *(const float4*)(wrow + k4 * 4);
            float2 wl = make_float2(w.x, w.y), wh = make_float2(w.z, w.w);
#pragma unroll
            for (int b = 0; b < 8; b++) {
                float4 hv = *(const float4*)(hb + b * HS + k4 * 4);
                fma2(acc[b], wl, make_float2(hv.x, hv.y));
                fma2(acc[b], wh, make_float2(hv.z, hv.w));
            }
        }
        float* psr = &ps[(ks * 128 + rr) * PS];
#pragma unroll
        for (int b = 0; b < 8; b++) psr[b] = acc[b].x + acc[b].y;
        __syncthreads();

        // finalize: gather 4 gates x 4 ks for (u, b0) and (u, b0+4)
        if (tid < 128) {
            float p0[4], p1[4];
#pragma unroll
            for (int g = 0; g < 4; g++) { p0[g] = xr0[g]; p1[g] = xr1[g]; }
#pragma unroll
            for (int s = 0; s < 4; s++) {
                const float* pp = &ps[(s * 128) * PS];
#pragma unroll
                for (int g = 0; g < 4; g++) {
                    const float* row = pp + (g * 32 + u) * PS;
                    p0[g] += row[bq];
                    p1[g] += row[bq + 4];
                }
            }
            c0 = fast_sigmoid(p0[1]) * c0 + fast_sigmoid(p0[0]) * fast_tanh(p0[2]);
            c1 = fast_sigmoid(p1[1]) * c1 + fast_sigmoid(p1[0]) * fast_tanh(p1[2]);
            h0v = fast_sigmoid(p0[3]) * fast_tanh(c0);
            h1v = fast_sigmoid(p1[3]) * fast_tanh(c1);

            uint32_t off0 = h_sh_base +
                (uint32_t)((((cur ^ 1) * 8 + bq) * HS + kglob) * 4);
            uint32_t off1 = h_sh_base +
                (uint32_t)((((cur ^ 1) * 8 + bq + 4) * HS + kglob) * 4);
#pragma unroll
            for (int r = 0; r < CL; r++) {
                st_remote_f32(off0, (uint32_t)r, h0v);
                st_remote_f32(off1, (uint32_t)r, h1v);
            }
        }
        // step barrier: release DSMEM writes, sync ps reuse, acquire peers' h
        asm volatile("barrier.cluster.arrive.aligned;" ::: "memory");
        asm volatile("barrier.cluster.wait.aligned;" ::: "memory");
    }

    if (tid < 128) {
        g_hf[b0 * HH + kglob] = h0v;
        g_hf[(b0 + 4) * HH + kglob] = h1v;
    }
}

// ---------------------------------------------------------------------------
// Final linear
// ---------------------------------------------------------------------------
__global__ void final_lin(const float* __restrict__ Wlin,
                          const float* __restrict__ blin,
                          float* __restrict__ out) {
    const int b = blockIdx.x;
    const int tid = threadIdx.x;
    __shared__ float s0[256];
    __shared__ float s1[256];

    float hf = g_hf[b * HH + tid];
    float hb = g_hb[b * HH + tid];
    s0[tid] = hf * Wlin[tid] + hb * Wlin[HH + tid];
    s1[tid] = hf * Wlin[512 + tid] + hb * Wlin[512 + HH + tid];
    __syncthreads();
    for (int off = 128; off > 0; off >>= 1) {
        if (tid < off) {
            s0[tid] += s0[tid + off];
            s1[tid] += s1[tid + off];
        }
        __syncthreads();
    }
    if (tid == 0) {
        out[b * 2 + 0] = s0[0] + blin[0];
        out[b * 2 + 1] = s1[0] + blin[1];
    }
}

// ---------------------------------------------------------------------------
extern "C" void kernel_launch(void* const* d_in, const int* in_sizes, int n_in,
                              void* d_out, int out_size) {
    const float* x      = (const float*)d_in[0];
    const float* W_ih_f = (const float*)d_in[1];
    const float* W_hh_f = (const float*)d_in[2];
    const float* b_f    = (const float*)d_in[3];
    const float* W_ih_b = (const float*)d_in[4];
    // d_in[5] = W_hh_b : unused (backward dir needs only its first step, h0=0)
    const float* b_b    = (const float*)d_in[6];
    const float* W_lin  = (const float*)d_in[7];
    const float* b_lin  = (const float*)d_in[8];
    float* out = (float*)d_out;

    const int smem_bytes = (128 * WS + 2 * 8 * HS + 4 * 128 * PS) * 4; // 188928
    cudaFuncSetAttribute(lstm_persist,
                         cudaFuncAttributeMaxDynamicSharedMemorySize, smem_bytes);

    xp_gemm<<<dim3(8, 512), 256>>>(x, W_ih_f, b_f);
    bwd_last<<<BB, 256>>>(x, W_ih_b, b_b);
    lstm_persist<<<NCLUS * CL, 512, smem_bytes>>>(W_hh_f);
    final_lin<<<BB, 256>>>(W_lin, b_lin, out);
}

// round 8
// speedup vs baseline: 1.3536x; 1.3536x over previous
#include <cuda_runtime.h>
#include <math.h>
#include <stdint.h>

// Problem dims
#define BB 128
#define TT 512
#define II 300
#define HH 256
#define G4 1024   // 4*H

// persist geometry
#define CL 8           // CTAs per cluster
#define NCLUS 16       // clusters
#define HS 264         // h_s row stride (floats): 8 mod 32 (h loads are broadcast)
#define PS 9           // ps batch stride (9 coprime 32 -> conflict-free)

// Scratch (device globals — no allocations allowed)
__device__ float g_xp[(size_t)TT * BB * G4];   // [t][b][gate]  (256 MB)
__device__ float g_hf[BB * HH];                // forward-dir final hidden
__device__ float g_hb[BB * HH];                // backward-dir final hidden

__device__ __forceinline__ float fast_sigmoid(float v) {
    return 1.0f / (1.0f + __expf(-v));
}
__device__ __forceinline__ float fast_tanh(float v) {
    return __fdividef(2.0f, 1.0f + __expf(-2.0f * v)) - 1.0f;
}

// packed dual-fp32 FMA
__device__ __forceinline__ void fma2(float2& acc, float2 a, float2 b) {
    asm("fma.rn.f32x2 %0, %1, %2, %0;"
        : "+l"(reinterpret_cast<unsigned long long&>(acc))
        : "l"(reinterpret_cast<unsigned long long&>(a)),
          "l"(reinterpret_cast<unsigned long long&>(b)));
}

__device__ __forceinline__ void st_remote_f32(uint32_t saddr, uint32_t trank, float v) {
    uint32_t ra;
    asm volatile("mapa.shared::cluster.u32 %0, %1, %2;" : "=r"(ra) : "r"(saddr), "r"(trank));
    asm volatile("st.shared::cluster.f32 [%0], %1;" :: "r"(ra), "f"(v) : "memory");
}

// ---------------------------------------------------------------------------
// xp GEMM: xp[t][b][n] = sum_i x[b][t][i] * W_ih_f[n][i] + b_f[n]
// ---------------------------------------------------------------------------
__global__ void xp_gemm(const float* __restrict__ A,
                        const float* __restrict__ W,
                        const float* __restrict__ bias) {
    __shared__ float As[8][132];
    __shared__ float Bs[8][132];

    const int nt = blockIdx.x;
    const int mt = blockIdx.y;
    const int tid = threadIdx.x;
    const int tx = tid & 15;
    const int ty = tid >> 4;

    const int m0 = mt * 128;
    const int n0 = nt * 128;

    float2 acc2[4][8];
#pragma unroll
    for (int ip = 0; ip < 4; ip++)
#pragma unroll
        for (int j = 0; j < 8; j++) acc2[ip][j] = make_float2(0.f, 0.f);

    for (int k0 = 0; k0 < II; k0 += 8) {
#pragma unroll
        for (int e = tid; e < 1024; e += 256) {
            int r = e >> 3;
            int kk = e & 7;
            int k = k0 + kk;
            As[kk][r] = (k < II) ? A[(size_t)(m0 + r) * II + k] : 0.0f;
            Bs[kk][r] = (k < II) ? W[(size_t)(n0 + r) * II + k] : 0.0f;
        }
        __syncthreads();

#pragma unroll
        for (int kk = 0; kk < 8; kk++) {
            float4 a0 = *(const float4*)&As[kk][ty * 8];
            float4 a1 = *(const float4*)&As[kk][ty * 8 + 4];
            float4 b0 = *(const float4*)&Bs[kk][tx * 8];
            float4 b1 = *(const float4*)&Bs[kk][tx * 8 + 4];
            float2 ap[4] = { {a0.x, a0.y}, {a0.z, a0.w}, {a1.x, a1.y}, {a1.z, a1.w} };
            float bj[8] = { b0.x, b0.y, b0.z, b0.w, b1.x, b1.y, b1.z, b1.w };
#pragma unroll
            for (int j = 0; j < 8; j++) {
                float2 bb = make_float2(bj[j], bj[j]);
#pragma unroll
                for (int ip = 0; ip < 4; ip++) fma2(acc2[ip][j], ap[ip], bb);
            }
        }
        __syncthreads();
    }

#pragma unroll
    for (int i = 0; i < 8; i++) {
        int m = m0 + ty * 8 + i;
        int bidx = m >> 9;
        int t = m & 511;
        size_t base = ((size_t)t * BB + bidx) * G4;
#pragma unroll
        for (int j = 0; j < 8; j++) {
            int n = n0 + tx * 8 + j;
            float v = (i & 1) ? acc2[i >> 1][j].y : acc2[i >> 1][j].x;
            g_xp[base + n] = v + bias[n];
        }
    }
}

// ---------------------------------------------------------------------------
// Backward direction: only ONE step matters (h0=c0=0 on x[:, T-1]).
// ---------------------------------------------------------------------------
__global__ void bwd_last(const float* __restrict__ x,
                         const float* __restrict__ Wb,
                         const float* __restrict__ bb) {
    const int b = blockIdx.x;
    const int tid = threadIdx.x;
    __shared__ float xs[304];
    __shared__ float gs[G4];

    const float* xr = x + ((size_t)b * TT + (TT - 1)) * II;
    for (int i = tid; i < II; i += 256) xs[i] = xr[i];
    __syncthreads();

    const int wid = tid >> 5;
    const int lane = tid & 31;
    for (int r = wid; r < G4; r += 8) {
        float s = 0.0f;
        const float* wr = Wb + (size_t)r * II;
        for (int i = lane; i < II; i += 32) s += xs[i] * wr[i];
#pragma unroll
        for (int off = 16; off > 0; off >>= 1)
            s += __shfl_down_sync(0xffffffffu, s, off);
        if (lane == 0) gs[r] = s + bb[r];
    }
    __syncthreads();

    if (tid < HH) {
        float ig = 1.0f / (1.0f + expf(-gs[tid]));
        float gg = tanhf(gs[512 + tid]);
        float og = 1.0f / (1.0f + expf(-gs[768 + tid]));
        float c = ig * gg;
        g_hb[b * HH + tid] = og * tanhf(c);
    }
}

// ---------------------------------------------------------------------------
// Persistent forward recurrence. 16 clusters x 8 CTAs; cluster = 8 batches.
// CTA rank owns gate rows {g*256 + rank*32 + u : g<4, u<32}. W for those rows
// lives in REGISTERS: thread (rr = tid&63, ks = tid>>6) holds rows lr=rr and
// lr=rr+64, K-chunk [ks*32, ks*32+32) -> 2 x 16 float2 = 64 regs, loaded from
// global ONCE. Step mainloop issues only h loads (smem broadcast) + fma2.
// Partials -> ps[8][128][PS]; finalize threads (tid<256: gb batch, gu unit)
// reduce 8 chunks, add prefetched xp, update register-resident c, scatter h
// to all 8 cluster CTAs via DSMEM; one barrier.cluster per step.
// ---------------------------------------------------------------------------
__global__ void __launch_bounds__(512, 1) __cluster_dims__(CL, 1, 1)
lstm_persist(const float* __restrict__ Whh) {
    extern __shared__ float sm[];
    float* h_s = sm;                          // [2][8][HS]
    float* ps  = sm + 2 * 8 * HS;             // [8][128][PS]

    const int tid = threadIdx.x;
    uint32_t rank;
    asm("mov.u32 %0, %%cluster_ctarank;" : "=r"(rank));
    const int cid = blockIdx.x >> 3;

    const int rr = tid & 63;                  // base row pair
    const int ks = tid >> 6;                  // 0..7 K chunk
    const int gb = tid >> 5;                  // finalize: batch (tid<256)
    const int gu = tid & 31;                  // finalize: hidden unit
    const int kglob = (int)rank * 32 + gu;

    // ---- W rows into registers (once) ----
    // local row lr -> global row (lr>>5)*256 + rank*32 + (lr&31)
    const int grow0 = (rr >> 5) * HH + (int)rank * 32 + (rr & 31);          // gates 0/1
    const int grow1 = ((rr + 64) >> 5) * HH + (int)rank * 32 + (rr & 31);   // gates 2/3
    float2 w0p[16], w1p[16];
    {
        const float2* w0 = (const float2*)(Whh + (size_t)grow0 * HH + ks * 32);
        const float2* w1 = (const float2*)(Whh + (size_t)grow1 * HH + ks * 32);
#pragma unroll
        for (int i = 0; i < 16; i++) { w0p[i] = __ldg(&w0[i]); w1p[i] = __ldg(&w1[i]); }
    }

    // zero h buffer 0 (buffer 1 fully overwritten every step)
    for (int i = tid; i < 8 * HS; i += 512) h_s[i] = 0.0f;
    __syncthreads();
    asm volatile("barrier.cluster.arrive.aligned;" ::: "memory");
    asm volatile("barrier.cluster.wait.aligned;" ::: "memory");

    float c_reg = 0.0f, h_last = 0.0f;
    const uint32_t h_sh_base = (uint32_t)__cvta_generic_to_shared(h_s);

    for (int t = 0; t < TT; t++) {
        const int cur = t & 1;
        const float* __restrict__ hb = h_s + cur * 8 * HS + ks * 32;

        // prefetch xp (finalize threads; consumed after mainloop)
        float xi = 0.f, xf = 0.f, xg = 0.f, xo = 0.f;
        if (tid < 256) {
            size_t xb = ((size_t)t * BB + cid * 8 + gb) * G4 + kglob;
            xi = __ldg(&g_xp[xb]);
            xf = __ldg(&g_xp[xb + 256]);
            xg = __ldg(&g_xp[xb + 512]);
            xo = __ldg(&g_xp[xb + 768]);
        }

        // mainloop: 2 rows x 8 batches x 32 k, W in registers.
        // Two 4-batch waves reusing ONE accumulator set (tight live range).
#pragma unroll
        for (int w = 0; w < 2; w++) {
            float2 a0[4], a1[4];
#pragma unroll
            for (int j = 0; j < 4; j++) {
                a0[j] = make_float2(0.f, 0.f);
                a1[j] = make_float2(0.f, 0.f);
            }
#pragma unroll
            for (int k4 = 0; k4 < 8; k4++) {
                float2 wl0 = w0p[k4 * 2], wh0 = w0p[k4 * 2 + 1];
                float2 wl1 = w1p[k4 * 2], wh1 = w1p[k4 * 2 + 1];
#pragma unroll
                for (int j = 0; j < 4; j++) {
                    float4 hv = *(const float4*)(hb + (w * 4 + j) * HS + k4 * 4);
                    float2 hl = make_float2(hv.x, hv.y);
                    float2 hh = make_float2(hv.z, hv.w);
                    fma2(a0[j], wl0, hl);
                    fma2(a0[j], wh0, hh);
                    fma2(a1[j], wl1, hl);
                    fma2(a1[j], wh1, hh);
                }
            }
#pragma unroll
            for (int j = 0; j < 4; j++) {
                ps[(ks * 128 + rr) * PS + w * 4 + j]      = a0[j].x + a0[j].y;
                ps[(ks * 128 + rr + 64) * PS + w * 4 + j] = a1[j].x + a1[j].y;
            }
        }
        __syncthreads();

        // finalize: reduce 8 k-chunks for (gb, gu), gates, DSMEM scatter
        if (tid < 256) {
            float pi = xi, pf = xf, pg = xg, po = xo;
#pragma unroll
            for (int s = 0; s < 8; s++) {
                const float* pp = &ps[(s * 128) * PS];
                pi += pp[(gu) * PS + gb];
                pf += pp[(32 + gu) * PS + gb];
                pg += pp[(64 + gu) * PS + gb];
                po += pp[(96 + gu) * PS + gb];
            }
            float ig = fast_sigmoid(pi);
            float fg = fast_sigmoid(pf);
            float gg = fast_tanh(pg);
            float og = fast_sigmoid(po);
            c_reg = fg * c_reg + ig * gg;
            float h = og * fast_tanh(c_reg);
            h_last = h;

            uint32_t off = h_sh_base +
                (uint32_t)((((cur ^ 1) * 8 + gb) * HS + kglob) * 4);
#pragma unroll
            for (int r = 0; r < CL; r++) st_remote_f32(off, (uint32_t)r, h);
        }
        // step barrier: release DSMEM writes, sync ps reuse, acquire peers' h
        asm volatile("barrier.cluster.arrive.aligned;" ::: "memory");
        asm volatile("barrier.cluster.wait.aligned;" ::: "memory");
    }

    if (tid < 256) {
        g_hf[(cid * 8 + gb) * HH + kglob] = h_last;
    }
}

// ---------------------------------------------------------------------------
// Final linear
// ---------------------------------------------------------------------------
__global__ void final_lin(const float* __restrict__ Wlin,
                          const float* __restrict__ blin,
                          float* __restrict__ out) {
    const int b = blockIdx.x;
    const int tid = threadIdx.x;
    __shared__ float s0[256];
    __shared__ float s1[256];

    float hf = g_hf[b * HH + tid];
    float hb = g_hb[b * HH + tid];
    s0[tid] = hf * Wlin[tid] + hb * Wlin[HH + tid];
    s1[tid] = hf * Wlin[512 + tid] + hb * Wlin[512 + HH + tid];
    __syncthreads();
    for (int off = 128; off > 0; off >>= 1) {
        if (tid < off) {
            s0[tid] += s0[tid + off];
            s1[tid] += s1[tid + off];
        }
        __syncthreads();
    }
    if (tid == 0) {
        out[b * 2 + 0] = s0[0] + blin[0];
        out[b * 2 + 1] = s1[0] + blin[1];
    }
}

// ---------------------------------------------------------------------------
extern "C" void kernel_launch(void* const* d_in, const int* in_sizes, int n_in,
                              void* d_out, int out_size) {
    const float* x      = (const float*)d_in[0];
    const float* W_ih_f = (const float*)d_in[1];
    const float* W_hh_f = (const float*)d_in[2];
    const float* b_f    = (const float*)d_in[3];
    const float* W_ih_b = (const float*)d_in[4];
    // d_in[5] = W_hh_b : unused (backward dir needs only its first step, h0=0)
    const float* b_b    = (const float*)d_in[6];
    const float* W_lin  = (const float*)d_in[7];
    const float* b_lin  = (const float*)d_in[8];
    float* out = (float*)d_out;

    const int smem_bytes = (2 * 8 * HS + 8 * 128 * PS) * 4;  // 53760
    cudaFuncSetAttribute(lstm_persist,
                         cudaFuncAttributeMaxDynamicSharedMemorySize, smem_bytes);

    xp_gemm<<<dim3(8, 512), 256>>>(x, W_ih_f, b_f);
    bwd_last<<<BB, 256>>>(x, W_ih_b, b_b);
    lstm_persist<<<NCLUS * CL, 512, smem_bytes>>>(W_hh_f);
    final_lin<<<BB, 256>>>(W_lin, b_lin, out);
}

// round 9
// speedup vs baseline: 1.4274x; 1.0545x over previous
#include <cuda_runtime.h>
#include <math.h>
#include <stdint.h>

// Problem dims
#define BB 128
#define TT 512
#define II 300
#define HH 256
#define G4 1024   // 4*H

// persist geometry
#define CL 8           // CTAs per cluster
#define NCLUS 16       // clusters
#define HS 264         // h_s row stride (floats): 8 mod 32 (h loads are broadcast)
#define PS 9           // ps batch stride (9 coprime 32 -> conflict-free)
#define HB_BYTES 8192u // bytes received per h buffer per step (8 CTAs x 1024 B)

// Scratch (device globals — no allocations allowed)
__device__ float g_xp[(size_t)TT * BB * G4];   // [t][b][gate]  (256 MB)
__device__ float g_hf[BB * HH];                // forward-dir final hidden
__device__ float g_hb[BB * HH];                // backward-dir final hidden

__device__ __forceinline__ float fast_sigmoid(float v) {
    return 1.0f / (1.0f + __expf(-v));
}
__device__ __forceinline__ float fast_tanh(float v) {
    return __fdividef(2.0f, 1.0f + __expf(-2.0f * v)) - 1.0f;
}

// packed dual-fp32 FMA
__device__ __forceinline__ void fma2(float2& acc, float2 a, float2 b) {
    asm("fma.rn.f32x2 %0, %1, %2, %0;"
        : "+l"(reinterpret_cast<unsigned long long&>(acc))
        : "l"(reinterpret_cast<unsigned long long&>(a)),
          "l"(reinterpret_cast<unsigned long long&>(b)));
}

__device__ __forceinline__ uint32_t mapa_u32(uint32_t saddr, uint32_t trank) {
    uint32_t ra;
    asm("mapa.shared::cluster.u32 %0, %1, %2;" : "=r"(ra) : "r"(saddr), "r"(trank));
    return ra;
}

// async remote store, byte-counted at the TARGET CTA's mbarrier
__device__ __forceinline__ void st_async_b64(uint32_t dst, uint64_t v, uint32_t mbar) {
    asm volatile("st.async.shared::cluster.mbarrier::complete_tx::bytes.b64 [%0], %1, [%2];"
                 :: "r"(dst), "l"(v), "r"(mbar) : "memory");
}

__device__ __forceinline__ void mbar_init(uint32_t mb, uint32_t count) {
    asm volatile("mbarrier.init.shared.b64 [%0], %1;" :: "r"(mb), "r"(count) : "memory");
}
__device__ __forceinline__ void mbar_arrive_expect_tx(uint32_t mb, uint32_t bytes) {
    asm volatile("mbarrier.arrive.expect_tx.shared.b64 _, [%0], %1;"
                 :: "r"(mb), "r"(bytes) : "memory");
}
__device__ __forceinline__ void mbar_wait_cluster(uint32_t mb, uint32_t parity) {
    asm volatile(
        "{\n\t.reg .pred p;\n\t"
        "WL_%=:\n\t"
        "mbarrier.try_wait.parity.acquire.cluster.shared::cta.b64 p, [%0], %1, 0x989680;\n\t"
        "@p bra.uni WD_%=;\n\t"
        "bra.uni WL_%=;\n\t"
        "WD_%=:\n\t}"
        :: "r"(mb), "r"(parity) : "memory");
}

// ---------------------------------------------------------------------------
// xp GEMM: xp[t][b][n] = sum_i x[b][t][i] * W_ih_f[n][i] + b_f[n]
// ---------------------------------------------------------------------------
__global__ void xp_gemm(const float* __restrict__ A,
                        const float* __restrict__ W,
                        const float* __restrict__ bias) {
    __shared__ float As[8][132];
    __shared__ float Bs[8][132];

    const int nt = blockIdx.x;
    const int mt = blockIdx.y;
    const int tid = threadIdx.x;
    const int tx = tid & 15;
    const int ty = tid >> 4;

    const int m0 = mt * 128;
    const int n0 = nt * 128;

    float2 acc2[4][8];
#pragma unroll
    for (int ip = 0; ip < 4; ip++)
#pragma unroll
        for (int j = 0; j < 8; j++) acc2[ip][j] = make_float2(0.f, 0.f);

    for (int k0 = 0; k0 < II; k0 += 8) {
#pragma unroll
        for (int e = tid; e < 1024; e += 256) {
            int r = e >> 3;
            int kk = e & 7;
            int k = k0 + kk;
            As[kk][r] = (k < II) ? A[(size_t)(m0 + r) * II + k] : 0.0f;
            Bs[kk][r] = (k < II) ? W[(size_t)(n0 + r) * II + k] : 0.0f;
        }
        __syncthreads();

#pragma unroll
        for (int kk = 0; kk < 8; kk++) {
            float4 a0 = *(const float4*)&As[kk][ty * 8];
            float4 a1 = *(const float4*)&As[kk][ty * 8 + 4];
            float4 b0 = *(const float4*)&Bs[kk][tx * 8];
            float4 b1 = *(const float4*)&Bs[kk][tx * 8 + 4];
            float2 ap[4] = { {a0.x, a0.y}, {a0.z, a0.w}, {a1.x, a1.y}, {a1.z, a1.w} };
            float bj[8] = { b0.x, b0.y, b0.z, b0.w, b1.x, b1.y, b1.z, b1.w };
#pragma unroll
            for (int j = 0; j < 8; j++) {
                float2 bb = make_float2(bj[j], bj[j]);
#pragma unroll
                for (int ip = 0; ip < 4; ip++) fma2(acc2[ip][j], ap[ip], bb);
            }
        }
        __syncthreads();
    }

#pragma unroll
    for (int i = 0; i < 8; i++) {
        int m = m0 + ty * 8 + i;
        int bidx = m >> 9;
        int t = m & 511;
        size_t base = ((size_t)t * BB + bidx) * G4;
#pragma unroll
        for (int j = 0; j < 8; j++) {
            int n = n0 + tx * 8 + j;
            float v = (i & 1) ? acc2[i >> 1][j].y : acc2[i >> 1][j].x;
            g_xp[base + n] = v + bias[n];
        }
    }
}

// ---------------------------------------------------------------------------
// Backward direction: only ONE step matters (h0=c0=0 on x[:, T-1]).
// ---------------------------------------------------------------------------
__global__ void bwd_last(const float* __restrict__ x,
                         const float* __restrict__ Wb,
                         const float* __restrict__ bb) {
    const int b = blockIdx.x;
    const int tid = threadIdx.x;
    __shared__ float xs[304];
    __shared__ float gs[G4];

    const float* xr = x + ((size_t)b * TT + (TT - 1)) * II;
    for (int i = tid; i < II; i += 256) xs[i] = xr[i];
    __syncthreads();

    const int wid = tid >> 5;
    const int lane = tid & 31;
    for (int r = wid; r < G4; r += 8) {
        float s = 0.0f;
        const float* wr = Wb + (size_t)r * II;
        for (int i = lane; i < II; i += 32) s += xs[i] * wr[i];
#pragma unroll
        for (int off = 16; off > 0; off >>= 1)
            s += __shfl_down_sync(0xffffffffu, s, off);
        if (lane == 0) gs[r] = s + bb[r];
    }
    __syncthreads();

    if (tid < HH) {
        float ig = 1.0f / (1.0f + expf(-gs[tid]));
        float gg = tanhf(gs[512 + tid]);
        float og = 1.0f / (1.0f + expf(-gs[768 + tid]));
        float c = ig * gg;
        g_hb[b * HH + tid] = og * tanhf(c);
    }
}

// ---------------------------------------------------------------------------
// Persistent forward recurrence: 16 clusters x 8 CTAs; cluster = 8 batches.
// W in registers (as R8). h exchanged with st.async.b64 + mbarrier
// complete_tx — NO per-step cluster barrier; each CTA proceeds the moment
// its 8192 expected bytes landed. Safety argument:
//  * ps reuse: mbar[b] completion requires MY OWN finalize sends, which are
//    ordered after my finalize ps reads (data dep), so next step's mainloop
//    ps writes (gated by the wait) cannot race step-t ps reads.
//  * re-arm race: peer's step t+1 sends into my mbar[cur] require their
//    t+1 wait, which requires my step-t sends; my tid0 re-arms mbar[cur]
//    before issuing its own step-t sends, so the re-arm always precedes
//    any arrival it must count.
//  * buffer reuse: peer's t+2 writes into h buffer[cur] require my t+1
//    sends, which follow my step-t reads of buffer[cur] (syncthreads).
// ---------------------------------------------------------------------------
__global__ void __launch_bounds__(512, 1) __cluster_dims__(CL, 1, 1)
lstm_persist(const float* __restrict__ Whh) {
    extern __shared__ float sm[];
    // layout: [0..16) two mbarriers; h_s at float index 4; ps after
    float* h_s = sm + 4;                      // [2][8][HS]
    float* ps  = h_s + 2 * 8 * HS;            // [8][128][PS]

    const int tid = threadIdx.x;
    uint32_t rank;
    asm("mov.u32 %0, %%cluster_ctarank;" : "=r"(rank));
    const int cid = blockIdx.x >> 3;

    const uint32_t smem_base = (uint32_t)__cvta_generic_to_shared(sm);
    const uint32_t mb0 = smem_base;           // mbarrier for h buffer 0
    const uint32_t mb1 = smem_base + 8;       // mbarrier for h buffer 1
    const uint32_t hbytes0 = smem_base + 16;  // h_s as byte address

    const int rr = tid & 63;                  // base row pair
    const int ks = tid >> 6;                  // 0..7 K chunk
    const int gb = tid >> 5;                  // finalize: batch (tid<256)
    const int gu = tid & 31;                  // finalize: hidden unit
    const int kglob = (int)rank * 32 + gu;

    // ---- W rows into registers (once) ----
    const int grow0 = (rr >> 5) * HH + (int)rank * 32 + (rr & 31);          // gates 0/1
    const int grow1 = ((rr + 64) >> 5) * HH + (int)rank * 32 + (rr & 31);   // gates 2/3
    float2 w0p[16], w1p[16];
    {
        const float2* w0 = (const float2*)(Whh + (size_t)grow0 * HH + ks * 32);
        const float2* w1 = (const float2*)(Whh + (size_t)grow1 * HH + ks * 32);
#pragma unroll
        for (int i = 0; i < 16; i++) { w0p[i] = __ldg(&w0[i]); w1p[i] = __ldg(&w1[i]); }
    }

    // zero h buffer 0; init mbarriers; arm mbar1 for step-0 sends
    for (int i = tid; i < 8 * HS; i += 512) h_s[i] = 0.0f;
    if (tid == 0) {
        mbar_init(mb0, 1);
        mbar_init(mb1, 1);
        mbar_arrive_expect_tx(mb1, HB_BYTES);
    }
    __syncthreads();
    // one-time cluster barrier: all peers' mbarriers initialized+armed
    asm volatile("barrier.cluster.arrive.aligned;" ::: "memory");
    asm volatile("barrier.cluster.wait.aligned;" ::: "memory");

    float c_reg = 0.0f, h_last = 0.0f;
    int ph0 = 0, ph1 = 0;

    for (int t = 0; t < TT; t++) {
        const int cur = t & 1;

        // wait for this step's h (skip t=0: buffer 0 pre-zeroed, no sends)
        if (t > 0) {
            if (cur) { mbar_wait_cluster(mb1, (uint32_t)ph1); ph1 ^= 1; }
            else     { mbar_wait_cluster(mb0, (uint32_t)ph0); ph0 ^= 1; }
        }

        const float* __restrict__ hb = h_s + cur * 8 * HS + ks * 32;

        // prefetch xp (finalize threads; consumed after mainloop)
        float xi = 0.f, xf = 0.f, xg = 0.f, xo = 0.f;
        if (tid < 256) {
            size_t xb = ((size_t)t * BB + cid * 8 + gb) * G4 + kglob;
            xi = __ldg(&g_xp[xb]);
            xf = __ldg(&g_xp[xb + 256]);
            xg = __ldg(&g_xp[xb + 512]);
            xo = __ldg(&g_xp[xb + 768]);
        }

        // mainloop: 2 rows x 8 batches x 32 k, W in registers
#pragma unroll
        for (int w = 0; w < 2; w++) {
            float2 a0[4], a1[4];
#pragma unroll
            for (int j = 0; j < 4; j++) {
                a0[j] = make_float2(0.f, 0.f);
                a1[j] = make_float2(0.f, 0.f);
            }
#pragma unroll
            for (int k4 = 0; k4 < 8; k4++) {
                float2 wl0 = w0p[k4 * 2], wh0 = w0p[k4 * 2 + 1];
                float2 wl1 = w1p[k4 * 2], wh1 = w1p[k4 * 2 + 1];
#pragma unroll
                for (int j = 0; j < 4; j++) {
                    float4 hv = *(const float4*)(hb + (w * 4 + j) * HS + k4 * 4);
                    float2 hl = make_float2(hv.x, hv.y);
                    float2 hh = make_float2(hv.z, hv.w);
                    fma2(a0[j], wl0, hl);
                    fma2(a0[j], wh0, hh);
                    fma2(a1[j], wl1, hl);
                    fma2(a1[j], wh1, hh);
                }
            }
#pragma unroll
            for (int j = 0; j < 4; j++) {
                ps[(ks * 128 + rr) * PS + w * 4 + j]      = a0[j].x + a0[j].y;
                ps[(ks * 128 + rr + 64) * PS + w * 4 + j] = a1[j].x + a1[j].y;
            }
        }
        __syncthreads();   // ps complete; also: all reads of h_s[cur] done

        // re-arm mbar[cur] for its next receive cycle (arrivals during t+1)
        if (tid == 0) {
            if (cur) mbar_arrive_expect_tx(mb1, HB_BYTES);
            else     mbar_arrive_expect_tx(mb0, HB_BYTES);
        }

        // finalize: reduce 8 k-chunks, gates, async scatter (b64 pairs)
        if (tid < 256) {
            float pi = xi, pf = xf, pg = xg, po = xo;
#pragma unroll
            for (int s = 0; s < 8; s++) {
                const float* pp = &ps[(s * 128) * PS];
                pi += pp[(gu) * PS + gb];
                pf += pp[(32 + gu) * PS + gb];
                pg += pp[(64 + gu) * PS + gb];
                po += pp[(96 + gu) * PS + gb];
            }
            float ig = fast_sigmoid(pi);
            float fg = fast_sigmoid(pf);
            float gg = fast_tanh(pg);
            float og = fast_sigmoid(po);
            c_reg = fg * c_reg + ig * gg;
            float h = og * fast_tanh(c_reg);
            h_last = h;

            // pack (gu even, gu odd) into b64; even lanes send
            float hnext = __shfl_down_sync(0xffffffffu, h, 1);
            if ((gu & 1) == 0) {
                uint64_t pkt = ((uint64_t)__float_as_uint(hnext) << 32) |
                               (uint64_t)__float_as_uint(h);
                uint32_t dstoff = hbytes0 +
                    (uint32_t)((((cur ^ 1) * 8 + gb) * HS + kglob) * 4);
                uint32_t mboff = (cur ^ 1) ? mb1 : mb0;
#pragma unroll
                for (int r = 0; r < CL; r++) {
                    uint32_t d = mapa_u32(dstoff, (uint32_t)r);
                    uint32_t m = mapa_u32(mboff, (uint32_t)r);
                    st_async_b64(d, pkt, m);
                }
            }
        }
        // no cluster barrier: next iteration's mbar wait is the sync point
    }

    // drain incoming step-511 sends (into buffer 0) before exit, so no peer
    // st.async targets a dead CTA's smem
    mbar_wait_cluster(mb0, (uint32_t)ph0);

    if (tid < 256) {
        g_hf[(cid * 8 + gb) * HH + kglob] = h_last;
    }
}

// ---------------------------------------------------------------------------
// Final linear
// ---------------------------------------------------------------------------
__global__ void final_lin(const float* __restrict__ Wlin,
                          const float* __restrict__ blin,
                          float* __restrict__ out) {
    const int b = blockIdx.x;
    const int tid = threadIdx.x;
    __shared__ float s0[256];
    __shared__ float s1[256];

    float hf = g_hf[b * HH + tid];
    float hb = g_hb[b * HH + tid];
    s0[tid] = hf * Wlin[tid] + hb * Wlin[HH + tid];
    s1[tid] = hf * Wlin[512 + tid] + hb * Wlin[512 + HH + tid];
    __syncthreads();
    for (int off = 128; off > 0; off >>= 1) {
        if (tid < off) {
            s0[tid] += s0[tid + off];
            s1[tid] += s1[tid + off];
        }
        __syncthreads();
    }
    if (tid == 0) {
        out[b * 2 + 0] = s0[0] + blin[0];
        out[b * 2 + 1] = s1[0] + blin[1];
    }
}

// ---------------------------------------------------------------------------
extern "C" void kernel_launch(void* const* d_in, const int* in_sizes, int n_in,
                              void* d_out, int out_size) {
    const float* x      = (const float*)d_in[0];
    const float* W_ih_f = (const float*)d_in[1];
    const float* W_hh_f = (const float*)d_in[2];
    const float* b_f    = (const float*)d_in[3];
    const float* W_ih_b = (const float*)d_in[4];
    // d_in[5] = W_hh_b : unused (backward dir needs only its first step, h0=0)
    const float* b_b    = (const float*)d_in[6];
    const float* W_lin  = (const float*)d_in[7];
    const float* b_lin  = (const float*)d_in[8];
    float* out = (float*)d_out;

    const int smem_bytes = 16 + (2 * 8 * HS + 8 * 128 * PS) * 4;  // 53776
    cudaFuncSetAttribute(lstm_persist,
                         cudaFuncAttributeMaxDynamicSharedMemorySize, smem_bytes);

    xp_gemm<<<dim3(8, 512), 256>>>(x, W_ih_f, b_f);
    bwd_last<<<BB, 256>>>(x, W_ih_b, b_b);
    lstm_persist<<<NCLUS * CL, 512, smem_bytes>>>(W_hh_f);
    final_lin<<<BB, 256>>>(W_lin, b_lin, out);
}

// round 11
// speedup vs baseline: 1.4379x; 1.0074x over previous
#include <cuda_runtime.h>
#include <math.h>
#include <stdint.h>

// Problem dims
#define BB 128
#define TT 512
#define II 300
#define HH 256
#define G4 1024   // 4*H

// persist geometry
#define CL 8           // CTAs per cluster
#define NCLUS 16       // clusters
#define HS 264         // h_s row stride (floats): 8 mod 32 (h loads are broadcast)
#define PS 9           // ps batch stride (9 coprime 32 -> conflict-free)
#define HB_BYTES 8192u // bytes received per h buffer per step (8 CTAs x 1024 B)

// Scratch (device globals — no allocations allowed)
__device__ float g_xp[(size_t)TT * BB * G4];   // [t][b][gate]  (256 MB)
__device__ float g_hf[BB * HH];                // forward-dir final hidden
__device__ float g_hb[BB * HH];                // backward-dir final hidden

__device__ __forceinline__ float fast_sigmoid(float v) {
    return 1.0f / (1.0f + __expf(-v));
}
__device__ __forceinline__ float fast_tanh(float v) {
    return __fdividef(2.0f, 1.0f + __expf(-2.0f * v)) - 1.0f;
}

// packed dual-fp32 FMA
__device__ __forceinline__ void fma2(float2& acc, float2 a, float2 b) {
    asm("fma.rn.f32x2 %0, %1, %2, %0;"
        : "+l"(reinterpret_cast<unsigned long long&>(acc))
        : "l"(reinterpret_cast<unsigned long long&>(a)),
          "l"(reinterpret_cast<unsigned long long&>(b)));
}

__device__ __forceinline__ uint32_t mapa_u32(uint32_t saddr, uint32_t trank) {
    uint32_t ra;
    asm("mapa.shared::cluster.u32 %0, %1, %2;" : "=r"(ra) : "r"(saddr), "r"(trank));
    return ra;
}

// async remote store, byte-counted at the TARGET CTA's mbarrier
__device__ __forceinline__ void st_async_b64(uint32_t dst, uint64_t v, uint32_t mbar) {
    asm volatile("st.async.shared::cluster.mbarrier::complete_tx::bytes.b64 [%0], %1, [%2];"
                 :: "r"(dst), "l"(v), "r"(mbar) : "memory");
}

__device__ __forceinline__ void mbar_init(uint32_t mb, uint32_t count) {
    asm volatile("mbarrier.init.shared.b64 [%0], %1;" :: "r"(mb), "r"(count) : "memory");
}
__device__ __forceinline__ void mbar_arrive_expect_tx(uint32_t mb, uint32_t bytes) {
    asm volatile("mbarrier.arrive.expect_tx.shared.b64 _, [%0], %1;"
                 :: "r"(mb), "r"(bytes) : "memory");
}
__device__ __forceinline__ void mbar_wait_cluster(uint32_t mb, uint32_t parity) {
    asm volatile(
        "{\n\t.reg .pred p;\n\t"
        "WL_%=:\n\t"
        "mbarrier.try_wait.parity.acquire.cluster.shared::cta.b64 p, [%0], %1, 0x989680;\n\t"
        "@p bra.uni WD_%=;\n\t"
        "bra.uni WL_%=;\n\t"
        "WD_%=:\n\t}"
        :: "r"(mb), "r"(parity) : "memory");
}

// ---------------------------------------------------------------------------
// xp GEMM: xp[t][b][n] = sum_i x[b][t][i] * W_ih_f[n][i] + b_f[n]
// ---------------------------------------------------------------------------
__global__ void xp_gemm(const float* __restrict__ A,
                        const float* __restrict__ W,
                        const float* __restrict__ bias) {
    __shared__ float As[8][132];
    __shared__ float Bs[8][132];

    const int nt = blockIdx.x;
    const int mt = blockIdx.y;
    const int tid = threadIdx.x;
    const int tx = tid & 15;
    const int ty = tid >> 4;

    const int m0 = mt * 128;
    const int n0 = nt * 128;

    float2 acc2[4][8];
#pragma unroll
    for (int ip = 0; ip < 4; ip++)
#pragma unroll
        for (int j = 0; j < 8; j++) acc2[ip][j] = make_float2(0.f, 0.f);

    for (int k0 = 0; k0 < II; k0 += 8) {
#pragma unroll
        for (int e = tid; e < 1024; e += 256) {
            int r = e >> 3;
            int kk = e & 7;
            int k = k0 + kk;
            As[kk][r] = (k < II) ? A[(size_t)(m0 + r) * II + k] : 0.0f;
            Bs[kk][r] = (k < II) ? W[(size_t)(n0 + r) * II + k] : 0.0f;
        }
        __syncthreads();

#pragma unroll
        for (int kk = 0; kk < 8; kk++) {
            float4 a0 = *(const float4*)&As[kk][ty * 8];
            float4 a1 = *(const float4*)&As[kk][ty * 8 + 4];
            float4 b0 = *(const float4*)&Bs[kk][tx * 8];
            float4 b1 = *(const float4*)&Bs[kk][tx * 8 + 4];
            float2 ap[4] = { {a0.x, a0.y}, {a0.z, a0.w}, {a1.x, a1.y}, {a1.z, a1.w} };
            float bj[8] = { b0.x, b0.y, b0.z, b0.w, b1.x, b1.y, b1.z, b1.w };
#pragma unroll
            for (int j = 0; j < 8; j++) {
                float2 bb = make_float2(bj[j], bj[j]);
#pragma unroll
                for (int ip = 0; ip < 4; ip++) fma2(acc2[ip][j], ap[ip], bb);
            }
        }
        __syncthreads();
    }

#pragma unroll
    for (int i = 0; i < 8; i++) {
        int m = m0 + ty * 8 + i;
        int bidx = m >> 9;
        int t = m & 511;
        size_t base = ((size_t)t * BB + bidx) * G4;
#pragma unroll
        for (int j = 0; j < 8; j++) {
            int n = n0 + tx * 8 + j;
            float v = (i & 1) ? acc2[i >> 1][j].y : acc2[i >> 1][j].x;
            g_xp[base + n] = v + bias[n];
        }
    }
}

// ---------------------------------------------------------------------------
// Backward direction: only ONE step matters (h0=c0=0 on x[:, T-1]).
// ---------------------------------------------------------------------------
__global__ void bwd_last(const float* __restrict__ x,
                         const float* __restrict__ Wb,
                         const float* __restrict__ bb) {
    const int b = blockIdx.x;
    const int tid = threadIdx.x;
    __shared__ float xs[304];
    __shared__ float gs[G4];

    const float* xr = x + ((size_t)b * TT + (TT - 1)) * II;
    for (int i = tid; i < II; i += 256) xs[i] = xr[i];
    __syncthreads();

    const int wid = tid >> 5;
    const int lane = tid & 31;
    for (int r = wid; r < G4; r += 8) {
        float s = 0.0f;
        const float* wr = Wb + (size_t)r * II;
        for (int i = lane; i < II; i += 32) s += xs[i] * wr[i];
#pragma unroll
        for (int off = 16; off > 0; off >>= 1)
            s += __shfl_down_sync(0xffffffffu, s, off);
        if (lane == 0) gs[r] = s + bb[r];
    }
    __syncthreads();

    if (tid < HH) {
        float ig = 1.0f / (1.0f + expf(-gs[tid]));
        float gg = tanhf(gs[512 + tid]);
        float og = 1.0f / (1.0f + expf(-gs[768 + tid]));
        float c = ig * gg;
        g_hb[b * HH + tid] = og * tanhf(c);
    }
}

// ---------------------------------------------------------------------------
// Persistent forward recurrence: 16 clusters x 8 CTAs; cluster = 8 batches.
// W in registers. h exchanged with st.async.b64 + mbarrier complete_tx (no
// per-step cluster barrier). xp prefetch is DOUBLE-BUFFERED — at step t we
// issue LDGs for step t+1 and consume values fetched during t-1, so bursty
// full-chip DRAM latency is covered by an entire step instead of only the
// mainloop. (Safety argument for the mbarrier protocol: see round 9.)
// ---------------------------------------------------------------------------
__global__ void __launch_bounds__(512, 1) __cluster_dims__(CL, 1, 1)
lstm_persist(const float* __restrict__ Whh) {
    extern __shared__ float sm[];
    // layout: [0..16) two mbarriers; h_s at float index 4; ps after
    float* h_s = sm + 4;                      // [2][8][HS]
    float* ps  = h_s + 2 * 8 * HS;            // [8][128][PS]

    const int tid = threadIdx.x;
    uint32_t rank;
    asm("mov.u32 %0, %%cluster_ctarank;" : "=r"(rank));
    const int cid = blockIdx.x >> 3;

    const uint32_t smem_base = (uint32_t)__cvta_generic_to_shared(sm);
    const uint32_t mb0 = smem_base;           // mbarrier for h buffer 0
    const uint32_t mb1 = smem_base + 8;       // mbarrier for h buffer 1
    const uint32_t hbytes0 = smem_base + 16;  // h_s as byte address

    const int rr = tid & 63;                  // base row pair
    const int ks = tid >> 6;                  // 0..7 K chunk
    const int gb = tid >> 5;                  // finalize: batch (tid<256)
    const int gu = tid & 31;                  // finalize: hidden unit
    const int kglob = (int)rank * 32 + gu;

    // ---- W rows into registers (once) ----
    const int grow0 = (rr >> 5) * HH + (int)rank * 32 + (rr & 31);          // gates 0/1
    const int grow1 = ((rr + 64) >> 5) * HH + (int)rank * 32 + (rr & 31);   // gates 2/3
    float2 w0p[16], w1p[16];
    {
        const float2* w0 = (const float2*)(Whh + (size_t)grow0 * HH + ks * 32);
        const float2* w1 = (const float2*)(Whh + (size_t)grow1 * HH + ks * 32);
#pragma unroll
        for (int i = 0; i < 16; i++) { w0p[i] = __ldg(&w0[i]); w1p[i] = __ldg(&w1[i]); }
    }

    // xp base for this thread's (batch, unit); stride per t is BB*G4
    const size_t xstep = (size_t)BB * G4;
    const float* xp_base = g_xp + (size_t)(cid * 8 + gb) * G4 + kglob;

    // preload xp for t=0 (overlaps W loads / init)
    float xi = 0.f, xf = 0.f, xg = 0.f, xo = 0.f;
    if (tid < 256) {
        xi = __ldg(xp_base + 0);
        xf = __ldg(xp_base + 256);
        xg = __ldg(xp_base + 512);
        xo = __ldg(xp_base + 768);
    }

    // zero h buffer 0; init mbarriers; arm mbar1 for step-0 sends
    for (int i = tid; i < 8 * HS; i += 512) h_s[i] = 0.0f;
    if (tid == 0) {
        mbar_init(mb0, 1);
        mbar_init(mb1, 1);
        mbar_arrive_expect_tx(mb1, HB_BYTES);
    }
    __syncthreads();
    // one-time cluster barrier: all peers' mbarriers initialized+armed
    asm volatile("barrier.cluster.arrive.aligned;" ::: "memory");
    asm volatile("barrier.cluster.wait.aligned;" ::: "memory");

    float c_reg = 0.0f, h_last = 0.0f;
    int ph0 = 0, ph1 = 0;

    for (int t = 0; t < TT; t++) {
        const int cur = t & 1;

        // wait for this step's h (skip t=0: buffer 0 pre-zeroed, no sends)
        if (t > 0) {
            if (cur) { mbar_wait_cluster(mb1, (uint32_t)ph1); ph1 ^= 1; }
            else     { mbar_wait_cluster(mb0, (uint32_t)ph0); ph0 ^= 1; }
        }

        // issue NEXT step's xp loads now: a full step of latency cover
        float nxi = 0.f, nxf = 0.f, nxg = 0.f, nxo = 0.f;
        if (tid < 256 && t + 1 < TT) {
            const float* nb = xp_base + (size_t)(t + 1) * xstep;
            nxi = __ldg(nb + 0);
            nxf = __ldg(nb + 256);
            nxg = __ldg(nb + 512);
            nxo = __ldg(nb + 768);
        }

        const float* __restrict__ hb = h_s + cur * 8 * HS + ks * 32;

        // mainloop: 2 rows x 8 batches x 32 k, W in registers
#pragma unroll
        for (int w = 0; w < 2; w++) {
            float2 a0[4], a1[4];
#pragma unroll
            for (int j = 0; j < 4; j++) {
                a0[j] = make_float2(0.f, 0.f);
                a1[j] = make_float2(0.f, 0.f);
            }
#pragma unroll
            for (int k4 = 0; k4 < 8; k4++) {
                float2 wl0 = w0p[k4 * 2], wh0 = w0p[k4 * 2 + 1];
                float2 wl1 = w1p[k4 * 2], wh1 = w1p[k4 * 2 + 1];
#pragma unroll
                for (int j = 0; j < 4; j++) {
                    float4 hv = *(const float4*)(hb + (w * 4 + j) * HS + k4 * 4);
                    float2 hl = make_float2(hv.x, hv.y);
                    float2 hh = make_float2(hv.z, hv.w);
                    fma2(a0[j], wl0, hl);
                    fma2(a0[j], wh0, hh);
                    fma2(a1[j], wl1, hl);
                    fma2(a1[j], wh1, hh);
                }
            }
#pragma unroll
            for (int j = 0; j < 4; j++) {
                ps[(ks * 128 + rr) * PS + w * 4 + j]      = a0[j].x + a0[j].y;
                ps[(ks * 128 + rr + 64) * PS + w * 4 + j] = a1[j].x + a1[j].y;
            }
        }
        __syncthreads();   // ps complete; also: all reads of h_s[cur] done

        // re-arm mbar[cur] for its next receive cycle (arrivals during t+1)
        if (tid == 0) {
            if (cur) mbar_arrive_expect_tx(mb1, HB_BYTES);
            else     mbar_arrive_expect_tx(mb0, HB_BYTES);
        }

        // finalize: reduce 8 k-chunks, gates, async scatter (b64 pairs)
        if (tid < 256) {
            float pi = xi, pf = xf, pg = xg, po = xo;
#pragma unroll
            for (int s = 0; s < 8; s++) {
                const float* pp = &ps[(s * 128) * PS];
                pi += pp[(gu) * PS + gb];
                pf += pp[(32 + gu) * PS + gb];
                pg += pp[(64 + gu) * PS + gb];
                po += pp[(96 + gu) * PS + gb];
            }
            float ig = fast_sigmoid(pi);
            float fg = fast_sigmoid(pf);
            float gg = fast_tanh(pg);
            float og = fast_sigmoid(po);
            c_reg = fg * c_reg + ig * gg;
            float h = og * fast_tanh(c_reg);
            h_last = h;

            // pack (gu even, gu odd) into b64; even lanes send
            float hnext = __shfl_down_sync(0xffffffffu, h, 1);
            if ((gu & 1) == 0) {
                uint64_t pkt = ((uint64_t)__float_as_uint(hnext) << 32) |
                               (uint64_t)__float_as_uint(h);
                uint32_t dstoff = hbytes0 +
                    (uint32_t)((((cur ^ 1) * 8 + gb) * HS + kglob) * 4);
                uint32_t mboff = (cur ^ 1) ? mb1 : mb0;
#pragma unroll
                for (int r = 0; r < CL; r++) {
                    uint32_t d = mapa_u32(dstoff, (uint32_t)r);
                    uint32_t m = mapa_u32(mboff, (uint32_t)r);
                    st_async_b64(d, pkt, m);
                }
            }
        }
        // rotate xp double buffer
        xi = nxi; xf = nxf; xg = nxg; xo = nxo;
        // no cluster barrier: next iteration's mbar wait is the sync point
    }

    // drain incoming step-511 sends (into buffer 0) before exit
    mbar_wait_cluster(mb0, (uint32_t)ph0);

    if (tid < 256) {
        g_hf[(cid * 8 + gb) * HH + kglob] = h_last;
    }
}

// ---------------------------------------------------------------------------
// Final linear
// ---------------------------------------------------------------------------
__global__ void final_lin(const float* __restrict__ Wlin,
                          const float* __restrict__ blin,
                          float* __restrict__ out) {
    const int b = blockIdx.x;
    const int tid = threadIdx.x;
    __shared__ float s0[256];
    __shared__ float s1[256];

    float hf = g_hf[b * HH + tid];
    float hb = g_hb[b * HH + tid];
    s0[tid] = hf * Wlin[tid] + hb * Wlin[HH + tid];
    s1[tid] = hf * Wlin[512 + tid] + hb * Wlin[512 + HH + tid];
    __syncthreads();
    for (int off = 128; off > 0; off >>= 1) {
        if (tid < off) {
            s0[tid] += s0[tid + off];
            s1[tid] += s1[tid + off];
        }
        __syncthreads();
    }
    if (tid == 0) {
        out[b * 2 + 0] = s0[0] + blin[0];
        out[b * 2 + 1] = s1[0] + blin[1];
    }
}

// ---------------------------------------------------------------------------
extern "C" void kernel_launch(void* const* d_in, const int* in_sizes, int n_in,
                              void* d_out, int out_size) {
    const float* x      = (const float*)d_in[0];
    const float* W_ih_f = (const float*)d_in[1];
    const float* W_hh_f = (const float*)d_in[2];
    const float* b_f    = (const float*)d_in[3];
    const float* W_ih_b = (const float*)d_in[4];
    // d_in[5] = W_hh_b : unused (backward dir needs only its first step, h0=0)
    const float* b_b    = (const float*)d_in[6];
    const float* W_lin  = (const float*)d_in[7];
    const float* b_lin  = (const float*)d_in[8];
    float* out = (float*)d_out;

    const int smem_bytes = 16 + (2 * 8 * HS + 8 * 128 * PS) * 4;  // 53776
    cudaFuncSetAttribute(lstm_persist,
                         cudaFuncAttributeMaxDynamicSharedMemorySize, smem_bytes);

    xp_gemm<<<dim3(8, 512), 256>>>(x, W_ih_f, b_f);
    bwd_last<<<BB, 256>>>(x, W_ih_b, b_b);
    lstm_persist<<<NCLUS * CL, 512, smem_bytes>>>(W_hh_f);
    final_lin<<<BB, 256>>>(W_lin, b_lin, out);
}